// round 12
// baseline (speedup 1.0000x reference)
#include <cuda_runtime.h>

#define N_NODES 100000
#define N_EDGES 1600000
#define D 128
#define SCAN_BLOCKS 98   // ceil(100000/1024)

// ---------------- scratch (static __device__, no allocation) ----------------
__device__ unsigned g_pb[(size_t)N_NODES * 64]; // X @ W_l as packed bf16x2 (agg operand)
__device__ float    g_q[(size_t)N_NODES * D];   // X @ W_r   (root path, fp32)
__device__ float    g_h[(size_t)N_NODES * D];   // layer-1 output
__device__ int      g_cnt[N_NODES];
__device__ int      g_offs[N_NODES + 1];
__device__ int      g_cursor[N_NODES];
__device__ int      g_bsums[SCAN_BLOCKS];
__device__ int      g_is64;
__device__ int      g_esrc[N_EDGES];

// ---------------- packing helpers --------------------------------------------
__device__ __forceinline__ unsigned pack_f16x2(float lo, float hi) {
    unsigned r;
    asm("cvt.rn.f16x2.f32 %0, %1, %2;" : "=r"(r) : "f"(hi), "f"(lo));   // hi->[31:16], lo->[15:0]
    return r;
}
__device__ __forceinline__ unsigned pack_bf16x2(float lo, float hi) {
    unsigned r;
    asm("cvt.rn.bf16x2.f32 %0, %1, %2;" : "=r"(r) : "f"(hi), "f"(lo));
    return r;
}
__device__ __forceinline__ float bf_lo(unsigned u) { return __uint_as_float(u << 16); }
__device__ __forceinline__ float bf_hi(unsigned u) { return __uint_as_float(u & 0xffff0000u); }

// fp16 MMA m16n8k16, fp32 accumulate
__device__ __forceinline__ void mma_f16(float c[4], const unsigned a[4], const unsigned b[2]) {
    asm volatile(
        "mma.sync.aligned.m16n8k16.row.col.f32.f16.f16.f32 "
        "{%0,%1,%2,%3}, {%4,%5,%6,%7}, {%8,%9}, {%0,%1,%2,%3};\n"
        : "+f"(c[0]), "+f"(c[1]), "+f"(c[2]), "+f"(c[3])
        : "r"(a[0]), "r"(a[1]), "r"(a[2]), "r"(a[3]), "r"(b[0]), "r"(b[1]));
}

// ---------------- edge-index dtype detect + counter zero (merged) ------------
__global__ void k_detect(const int* __restrict__ e) {
    int i = blockIdx.x * blockDim.x + threadIdx.x;
    if (i < N_NODES) g_cnt[i] = 0;
    if (blockIdx.x == 0) {
        __shared__ int nz;
        if (threadIdx.x == 0) nz = 0;
        __syncthreads();
        if (e[2 * threadIdx.x + 1] != 0) atomicAdd(&nz, 1);
        __syncthreads();
        if (threadIdx.x == 0) g_is64 = (nz == 0) ? 1 : 0;
    }
}

__device__ __forceinline__ int load_idx(const int* __restrict__ e, long long pos, int is64) {
    return is64 ? e[2 * pos] : e[pos];
}

// ---------------- CSR build --------------------------------------------------
__global__ void k_hist(const int* __restrict__ e) {
    int i = blockIdx.x * blockDim.x + threadIdx.x;
    if (i < N_EDGES) {
        int d = load_idx(e, (long long)N_EDGES + i, g_is64);
        atomicAdd(&g_cnt[d], 1);
    }
}

__global__ void k_scan_blocks(int n) {
    __shared__ int s[1024];
    int i = blockIdx.x * 1024 + threadIdx.x;
    int v = (i < n) ? g_cnt[i] : 0;
    s[threadIdx.x] = v;
    __syncthreads();
    #pragma unroll
    for (int d = 1; d < 1024; d <<= 1) {
        int t = (threadIdx.x >= d) ? s[threadIdx.x - d] : 0;
        __syncthreads();
        s[threadIdx.x] += t;
        __syncthreads();
    }
    if (i < n) g_offs[i] = s[threadIdx.x] - v;      // exclusive within block
    if (threadIdx.x == 1023) g_bsums[blockIdx.x] = s[1023];
}

__global__ void k_add_offs(int n, int e) {
    __shared__ int base;
    if (threadIdx.x < 32) {
        int b = blockIdx.x;
        int acc = 0;
        #pragma unroll
        for (int j = 0; j < 4; j++) {
            int idx = j * 32 + threadIdx.x;
            if (idx < b) acc += g_bsums[idx];
        }
        #pragma unroll
        for (int o = 16; o > 0; o >>= 1)
            acc += __shfl_down_sync(0xffffffffu, acc, o);
        if (threadIdx.x == 0) base = acc;
    }
    __syncthreads();
    int i = blockIdx.x * 1024 + threadIdx.x;
    if (i < n) {
        int o = g_offs[i] + base;
        g_offs[i] = o;
        g_cursor[i] = o;
    }
    if (i == 0) g_offs[n] = e;
}

__global__ void k_fill(const int* __restrict__ e) {
    int i = blockIdx.x * blockDim.x + threadIdx.x;
    if (i >= N_EDGES) return;
    int is64 = g_is64;
    int d = load_idx(e, (long long)N_EDGES + i, is64);
    int s = load_idx(e, (long long)i, is64);
    int pos = atomicAdd(&g_cursor[d], 1);
    g_esrc[pos] = s;
}

// ---------------- GEMM (fp16 mma): blockIdx.y=0 -> Pb=bf16(X@Wl); 1 -> Q=X@Wr
// 256 threads, 8 warps, per-block tile M=128 x N=128, double-buffered K pipe.
// 2 CTAs/SM (regs<=128): co-resident blocks hide each other's sync/LDG stalls.
// As[2][128 rows][12 u32]  (row = 16 f16 pairs + pad; stride 12 conflict-free)
// Bs[2][8 kp][128 n +8 pad] (warp-uniform kp -> conflict-free STS.128;
//                            frag addr = tig*136+col -> banks 8*tig+gid, free)
#define AS_BUF 1536            // u32 per A buffer (128*12)
#define BS_BUF 1088            // u32 per B buffer (8*136)

__global__ __launch_bounds__(256, 2) void k_gemm2(const float* __restrict__ Xe, int xsel,
                                                  const float* __restrict__ Wl,
                                                  const float* __restrict__ Wr, int n) {
    __shared__ unsigned As[2 * AS_BUF];
    __shared__ unsigned Bs[2 * BS_BUF];
    const float* __restrict__ X = xsel ? g_h : Xe;
    int mat = blockIdx.y;
    const float* __restrict__ W = mat ? Wr : Wl;

    int tid = threadIdx.x;
    int wid = tid >> 5, lane = tid & 31;
    int wm = wid >> 1;              // 0..3  (row tile)
    int wn = wid & 1;               // 0..1  (col tile)
    int gid = lane >> 2, tig = lane & 3;
    int row0 = blockIdx.x * 128;

    float c[2][8][4];
    #pragma unroll
    for (int mi = 0; mi < 2; mi++)
        #pragma unroll
        for (int ni = 0; ni < 8; ni++)
            #pragma unroll
            for (int j = 0; j < 4; j++) c[mi][ni][j] = 0.f;

    // A loader: row arow, 8 consecutive k (two float4)
    int arow = tid >> 1;            // 0..127
    int acol8 = (tid & 1) * 8;      // 0 or 8
    // B loader: warp kp handles k-pair {2kp, 2kp+1}, lane covers 4 n
    int kp = wid;                   // 0..7
    int n4 = lane * 4;              // 0..124

    const float* xr = X + (size_t)(row0 + arow) * 128 + acol8;
    bool aval = (row0 + arow) < n;

    float4 ra0, ra1, rb0, rb1;      // prefetch regs

    // ---- prologue: chunk 0 load+store, chunk 1 load ----
    ra0 = aval ? *(const float4*)(xr) : make_float4(0.f, 0.f, 0.f, 0.f);
    ra1 = aval ? *(const float4*)(xr + 4) : make_float4(0.f, 0.f, 0.f, 0.f);
    rb0 = *(const float4*)(W + (size_t)(2 * kp) * 128 + n4);
    rb1 = *(const float4*)(W + (size_t)(2 * kp + 1) * 128 + n4);
    {
        *(uint4*)(As + arow * 12 + (acol8 >> 1)) =
            make_uint4(pack_f16x2(ra0.x, ra0.y), pack_f16x2(ra0.z, ra0.w),
                       pack_f16x2(ra1.x, ra1.y), pack_f16x2(ra1.z, ra1.w));
        *(uint4*)(Bs + kp * 136 + n4) =
            make_uint4(pack_f16x2(rb0.x, rb1.x), pack_f16x2(rb0.y, rb1.y),
                       pack_f16x2(rb0.z, rb1.z), pack_f16x2(rb0.w, rb1.w));
    }
    ra0 = aval ? *(const float4*)(xr + 16) : make_float4(0.f, 0.f, 0.f, 0.f);
    ra1 = aval ? *(const float4*)(xr + 20) : make_float4(0.f, 0.f, 0.f, 0.f);
    rb0 = *(const float4*)(W + (size_t)(16 + 2 * kp) * 128 + n4);
    rb1 = *(const float4*)(W + (size_t)(16 + 2 * kp + 1) * 128 + n4);
    __syncthreads();

    #pragma unroll
    for (int ci = 0; ci < 8; ci++) {
        int cur = ci & 1, nxt = cur ^ 1;

        // STS chunk ci+1 (regs -> buf nxt)
        if (ci < 7) {
            *(uint4*)(As + nxt * AS_BUF + arow * 12 + (acol8 >> 1)) =
                make_uint4(pack_f16x2(ra0.x, ra0.y), pack_f16x2(ra0.z, ra0.w),
                           pack_f16x2(ra1.x, ra1.y), pack_f16x2(ra1.z, ra1.w));
            *(uint4*)(Bs + nxt * BS_BUF + kp * 136 + n4) =
                make_uint4(pack_f16x2(rb0.x, rb1.x), pack_f16x2(rb0.y, rb1.y),
                           pack_f16x2(rb0.z, rb1.z), pack_f16x2(rb0.w, rb1.w));
        }
        // LDG chunk ci+2 into regs
        if (ci < 6) {
            int kk = (ci + 2) * 16;
            ra0 = aval ? *(const float4*)(xr + kk) : make_float4(0.f, 0.f, 0.f, 0.f);
            ra1 = aval ? *(const float4*)(xr + kk + 4) : make_float4(0.f, 0.f, 0.f, 0.f);
            rb0 = *(const float4*)(W + (size_t)(kk + 2 * kp) * 128 + n4);
            rb1 = *(const float4*)(W + (size_t)(kk + 2 * kp + 1) * 128 + n4);
        }

        // MMA over buf cur: one k16 step
        const unsigned* Ac = As + cur * AS_BUF;
        const unsigned* Bc = Bs + cur * BS_BUF;
        {
            unsigned a[2][4], b[8][2];
            #pragma unroll
            for (int mi = 0; mi < 2; mi++) {
                int r = wm * 32 + mi * 16 + gid;
                a[mi][0] = Ac[r * 12 + tig];
                a[mi][1] = Ac[(r + 8) * 12 + tig];
                a[mi][2] = Ac[r * 12 + tig + 4];
                a[mi][3] = Ac[(r + 8) * 12 + tig + 4];
            }
            #pragma unroll
            for (int ni = 0; ni < 8; ni++) {
                int col = wn * 64 + ni * 8 + gid;
                b[ni][0] = Bc[tig * 136 + col];
                b[ni][1] = Bc[(tig + 4) * 136 + col];
            }
            #pragma unroll
            for (int mi = 0; mi < 2; mi++)
                #pragma unroll
                for (int ni = 0; ni < 8; ni++)
                    mma_f16(c[mi][ni], a[mi], b[ni]);
        }
        if (ci < 7) __syncthreads();
    }

    // epilogue
    if (mat == 0) {
        #pragma unroll
        for (int mi = 0; mi < 2; mi++) {
            int r = row0 + wm * 32 + mi * 16 + gid;
            #pragma unroll
            for (int ni = 0; ni < 8; ni++) {
                int cl = wn * 64 + ni * 8 + tig * 2;
                if (r < n)
                    g_pb[(size_t)r * 64 + (cl >> 1)] = pack_bf16x2(c[mi][ni][0], c[mi][ni][1]);
                if (r + 8 < n)
                    g_pb[(size_t)(r + 8) * 64 + (cl >> 1)] = pack_bf16x2(c[mi][ni][2], c[mi][ni][3]);
            }
        }
    } else {
        #pragma unroll
        for (int mi = 0; mi < 2; mi++) {
            int r = row0 + wm * 32 + mi * 16 + gid;
            #pragma unroll
            for (int ni = 0; ni < 8; ni++) {
                int cl = wn * 64 + ni * 8 + tig * 2;
                if (r < n)
                    *(float2*)(g_q + (size_t)r * 128 + cl) = make_float2(c[mi][ni][0], c[mi][ni][1]);
                if (r + 8 < n)
                    *(float2*)(g_q + (size_t)(r + 8) * 128 + cl) = make_float2(c[mi][ni][2], c[mi][ni][3]);
            }
        }
    }
}

// ---------------- aggregation: out = [relu]( mean_agg(Pb) + b + Q ) ---------
__global__ void k_agg(const float* __restrict__ bias, float* __restrict__ oext,
                      int osel, int do_relu) {
    int w = (blockIdx.x * blockDim.x + threadIdx.x) >> 5;
    if (w >= N_NODES) return;
    const unsigned* __restrict__ P = g_pb;
    const float* __restrict__ Q = g_q;
    float* __restrict__ out = osel ? oext : g_h;

    int lane = threadIdx.x & 31;
    int s0 = g_offs[w], s1 = g_offs[w + 1];

    float4 acc0 = make_float4(0.f, 0.f, 0.f, 0.f);
    float4 acc1 = make_float4(0.f, 0.f, 0.f, 0.f);
    int e = s0;
    for (; e + 8 <= s1; e += 8) {
        int idx[8];
        #pragma unroll
        for (int j = 0; j < 8; j++) idx[j] = g_esrc[e + j];
        uint2 u[8];
        #pragma unroll
        for (int j = 0; j < 8; j++)
            u[j] = ((const uint2*)(P + (size_t)idx[j] * 64))[lane];
        #pragma unroll
        for (int j = 0; j < 8; j += 2) {
            acc0.x += bf_lo(u[j].x) + bf_lo(u[j + 1].x);
            acc0.y += bf_hi(u[j].x) + bf_hi(u[j + 1].x);
            acc0.z += bf_lo(u[j].y) + bf_lo(u[j + 1].y);
            acc0.w += bf_hi(u[j].y) + bf_hi(u[j + 1].y);
        }
    }
    for (; e + 2 <= s1; e += 2) {
        int i0 = g_esrc[e], i1 = g_esrc[e + 1];
        uint2 u0 = ((const uint2*)(P + (size_t)i0 * 64))[lane];
        uint2 u1 = ((const uint2*)(P + (size_t)i1 * 64))[lane];
        acc1.x += bf_lo(u0.x) + bf_lo(u1.x);
        acc1.y += bf_hi(u0.x) + bf_hi(u1.x);
        acc1.z += bf_lo(u0.y) + bf_lo(u1.y);
        acc1.w += bf_hi(u0.y) + bf_hi(u1.y);
    }
    if (e < s1) {
        int i0 = g_esrc[e];
        uint2 u0 = ((const uint2*)(P + (size_t)i0 * 64))[lane];
        acc1.x += bf_lo(u0.x); acc1.y += bf_hi(u0.x);
        acc1.z += bf_lo(u0.y); acc1.w += bf_hi(u0.y);
    }
    acc0.x += acc1.x; acc0.y += acc1.y; acc0.z += acc1.z; acc0.w += acc1.w;

    int deg = s1 - s0;
    float scale = 1.0f / (float)(deg > 0 ? deg : 1);
    float4 qv = ((const float4*)(Q + (size_t)w * 128))[lane];
    float4 bv = ((const float4*)bias)[lane];
    float4 r;
    r.x = fmaf(acc0.x, scale, bv.x + qv.x);
    r.y = fmaf(acc0.y, scale, bv.y + qv.y);
    r.z = fmaf(acc0.z, scale, bv.z + qv.z);
    r.w = fmaf(acc0.w, scale, bv.w + qv.w);
    if (do_relu) {
        r.x = fmaxf(r.x, 0.f); r.y = fmaxf(r.y, 0.f);
        r.z = fmaxf(r.z, 0.f); r.w = fmaxf(r.w, 0.f);
    }
    ((float4*)(out + (size_t)w * 128))[lane] = r;
}

// ---------------- launch -----------------------------------------------------
// Fork/join: CSR build runs concurrently with the tensor-bound GEMM1.
// Streams/events created EXACTLY ONCE (first call = correctness run); reused by
// the capture call -> no driver-pool growth can outlive graph teardown.
extern "C" void kernel_launch(void* const* d_in, const int* in_sizes, int n_in,
                              void* d_out, int out_size) {
    const float* x   = (const float*)d_in[0];
    const int*   ei  = (const int*)d_in[1];
    const float* W1l = (const float*)d_in[2];
    const float* b1  = (const float*)d_in[3];
    const float* W1r = (const float*)d_in[4];
    const float* W2l = (const float*)d_in[5];
    const float* b2  = (const float*)d_in[6];
    const float* W2r = (const float*)d_in[7];
    float* out = (float*)d_out;

    const dim3 GEMM_GRID((N_NODES + 127) / 128, 2);   // 782 x 2 (y = mat)
    const int EDGE_GRID = (N_EDGES + 255) / 256;
    const int AGG_GRID  = (N_NODES * 32 + 255) / 256;

    static cudaStream_t s1 = nullptr;
    static cudaEvent_t evFork = nullptr, evCSR = nullptr;
    if (s1 == nullptr) {
        cudaStreamCreateWithFlags(&s1, cudaStreamNonBlocking);
        cudaEventCreateWithFlags(&evFork, cudaEventDisableTiming);
        cudaEventCreateWithFlags(&evCSR, cudaEventDisableTiming);
    }

    // fork
    cudaEventRecord(evFork, 0);
    cudaStreamWaitEvent(s1, evFork, 0);

    // ---- branch A (s1): CSR build (dst-grouped pull lists) ----
    k_detect<<<(N_NODES + 255) / 256, 256, 0, s1>>>(ei);
    k_hist<<<EDGE_GRID, 256, 0, s1>>>(ei);
    k_scan_blocks<<<SCAN_BLOCKS, 1024, 0, s1>>>(N_NODES);
    k_add_offs<<<SCAN_BLOCKS, 1024, 0, s1>>>(N_NODES, N_EDGES);
    k_fill<<<EDGE_GRID, 256, 0, s1>>>(ei);
    cudaEventRecord(evCSR, s1);

    // ---- branch B (stream 0): layer-1 dual GEMM (independent of CSR) ----
    k_gemm2<<<GEMM_GRID, 256>>>(x, 0, W1l, W1r, N_NODES);

    // join, then the dependent chain
    cudaStreamWaitEvent(0, evCSR, 0);
    k_agg<<<AGG_GRID, 256>>>(b1, out, 0, 1);
    k_gemm2<<<GEMM_GRID, 256>>>((const float*)0, 1, W2l, W2r, N_NODES);
    k_agg<<<AGG_GRID, 256>>>(b2, out, 1, 0);
}

// round 13
// speedup vs baseline: 1.3639x; 1.3639x over previous
#include <cuda_runtime.h>

#define N_NODES 100000
#define N_EDGES 1600000
#define D 128
#define SCAN_BLOCKS 98   // ceil(100000/1024)

// ---------------- scratch (static __device__, no allocation) ----------------
__device__ unsigned g_pb[(size_t)N_NODES * 64]; // X @ W_l as packed bf16x2 (agg operand)
__device__ float    g_q[(size_t)N_NODES * D];   // X @ W_r   (root path, fp32)
__device__ unsigned g_hh[(size_t)N_NODES * 64]; // layer-1 output, packed f16x2
__device__ int      g_cnt[N_NODES];
__device__ int      g_offs[N_NODES + 1];
__device__ int      g_cursor[N_NODES];
__device__ int      g_bsums[SCAN_BLOCKS];
__device__ int      g_is64;
__device__ int      g_esrc[N_EDGES];

// ---------------- packing helpers --------------------------------------------
__device__ __forceinline__ unsigned pack_f16x2(float lo, float hi) {
    unsigned r;
    asm("cvt.rn.f16x2.f32 %0, %1, %2;" : "=r"(r) : "f"(hi), "f"(lo));   // hi->[31:16], lo->[15:0]
    return r;
}
__device__ __forceinline__ unsigned pack_bf16x2(float lo, float hi) {
    unsigned r;
    asm("cvt.rn.bf16x2.f32 %0, %1, %2;" : "=r"(r) : "f"(hi), "f"(lo));
    return r;
}
__device__ __forceinline__ float bf_lo(unsigned u) { return __uint_as_float(u << 16); }
__device__ __forceinline__ float bf_hi(unsigned u) { return __uint_as_float(u & 0xffff0000u); }

// fp16 MMA m16n8k16, fp32 accumulate
__device__ __forceinline__ void mma_f16(float c[4], const unsigned a[4], const unsigned b[2]) {
    asm volatile(
        "mma.sync.aligned.m16n8k16.row.col.f32.f16.f16.f32 "
        "{%0,%1,%2,%3}, {%4,%5,%6,%7}, {%8,%9}, {%0,%1,%2,%3};\n"
        : "+f"(c[0]), "+f"(c[1]), "+f"(c[2]), "+f"(c[3])
        : "r"(a[0]), "r"(a[1]), "r"(a[2]), "r"(a[3]), "r"(b[0]), "r"(b[1]));
}

// ---------------- edge-index dtype detect + counter zero (merged) ------------
__global__ void k_detect(const int* __restrict__ e) {
    int i = blockIdx.x * blockDim.x + threadIdx.x;
    if (i < N_NODES) g_cnt[i] = 0;
    if (blockIdx.x == 0) {
        __shared__ int nz;
        if (threadIdx.x == 0) nz = 0;
        __syncthreads();
        if (e[2 * threadIdx.x + 1] != 0) atomicAdd(&nz, 1);
        __syncthreads();
        if (threadIdx.x == 0) g_is64 = (nz == 0) ? 1 : 0;
    }
}

__device__ __forceinline__ int load_idx(const int* __restrict__ e, long long pos, int is64) {
    return is64 ? e[2 * pos] : e[pos];
}

// ---------------- CSR build --------------------------------------------------
__global__ void k_hist(const int* __restrict__ e) {
    int i = blockIdx.x * blockDim.x + threadIdx.x;
    if (i < N_EDGES) {
        int d = load_idx(e, (long long)N_EDGES + i, g_is64);
        atomicAdd(&g_cnt[d], 1);
    }
}

__global__ void k_scan_blocks(int n) {
    __shared__ int s[1024];
    int i = blockIdx.x * 1024 + threadIdx.x;
    int v = (i < n) ? g_cnt[i] : 0;
    s[threadIdx.x] = v;
    __syncthreads();
    #pragma unroll
    for (int d = 1; d < 1024; d <<= 1) {
        int t = (threadIdx.x >= d) ? s[threadIdx.x - d] : 0;
        __syncthreads();
        s[threadIdx.x] += t;
        __syncthreads();
    }
    if (i < n) g_offs[i] = s[threadIdx.x] - v;      // exclusive within block
    if (threadIdx.x == 1023) g_bsums[blockIdx.x] = s[1023];
}

__global__ void k_add_offs(int n, int e) {
    __shared__ int base;
    if (threadIdx.x < 32) {
        int b = blockIdx.x;
        int acc = 0;
        #pragma unroll
        for (int j = 0; j < 4; j++) {
            int idx = j * 32 + threadIdx.x;
            if (idx < b) acc += g_bsums[idx];
        }
        #pragma unroll
        for (int o = 16; o > 0; o >>= 1)
            acc += __shfl_down_sync(0xffffffffu, acc, o);
        if (threadIdx.x == 0) base = acc;
    }
    __syncthreads();
    int i = blockIdx.x * 1024 + threadIdx.x;
    if (i < n) {
        int o = g_offs[i] + base;
        g_offs[i] = o;
        g_cursor[i] = o;
    }
    if (i == 0) g_offs[n] = e;
}

__global__ void k_fill(const int* __restrict__ e) {
    int i = blockIdx.x * blockDim.x + threadIdx.x;
    if (i >= N_EDGES) return;
    int is64 = g_is64;
    int d = load_idx(e, (long long)N_EDGES + i, is64);
    int s = load_idx(e, (long long)i, is64);
    int pos = atomicAdd(&g_cursor[d], 1);
    g_esrc[pos] = s;
}

// ---------------- fused dual GEMM (fp16 mma): Pb = bf16(X@Wl), Q = X@Wr -----
// Round-11 structure (512 threads, 1 CTA/SM, double-buffered K pipe).
// A source: fp32 Xe (layer 1, cvt on load) or packed-f16x2 g_hh (layer 2,
// direct uint2 load, no cvt).
// As[2][128 rows][12 u32]  (row = 16 f16 + 8 pad; stride-12 is conflict-free)
// Bs[2][2 mats][128 n][12 u32] (per n: 8 u32 of {k even, k odd} f16 pairs)
#define AS_BUF 1536            // u32 per A buffer (128*12)
#define BS_BUF 3072            // u32 per B buffer (2*128*12)
#define BS_MAT 1536            // u32 per mat (128*12)
#define GEMM_SMEM 36864        // (2*1536 + 2*3072) * 4

__global__ __launch_bounds__(512) void k_gemm2(const float* __restrict__ Xe, int xsel,
                                               const float* __restrict__ Wl,
                                               const float* __restrict__ Wr, int n) {
    extern __shared__ unsigned sm[];
    unsigned* As = sm;
    unsigned* Bs = sm + 2 * AS_BUF;

    int tid = threadIdx.x;
    int wid = tid >> 5, lane = tid & 31;
    int mat = wid >> 3;             // 0 = P, 1 = Q
    int wm = (wid & 7) >> 1;        // 0..3  (row tile)
    int wn = wid & 1;               // 0..1  (col tile)
    int gid = lane >> 2, tig = lane & 3;
    int row0 = blockIdx.x * 128;

    float c[2][8][4];
    #pragma unroll
    for (int mi = 0; mi < 2; mi++)
        #pragma unroll
        for (int ni = 0; ni < 8; ni++)
            #pragma unroll
            for (int j = 0; j < 4; j++) c[mi][ni][j] = 0.f;

    // A loader: thread -> row arow, k-quad acol4 within 16-wide chunk
    int arow = tid >> 2;            // 0..127
    int acol4 = (tid & 3) * 4;      // 0,4,8,12
    // B loader: thread -> k-pair kp, n-pair n2
    int kp = tid >> 6;              // 0..7
    int n2 = (tid & 63) * 2;        // 0..126

    const float* xr = Xe + (size_t)(row0 + arow) * 128 + acol4;
    const unsigned* hr = g_hh + (size_t)(row0 + arow) * 64 + (acol4 >> 1);
    bool aval = (row0 + arow) < n;

    unsigned au0, au1;              // A prefetch (2 packed f16x2 = 4 halves)
    float4 rbl, rbr;                // B prefetch; {Wk0[n2],Wk0[n2+1],Wk1[n2],Wk1[n2+1]}

    // A-chunk load: k-offset kk -> 2 packed u32
    #define LOAD_A(kk)                                                          \
        do {                                                                    \
            if (xsel) {                                                         \
                uint2 u = aval ? *(const uint2*)(hr + ((kk) >> 1))              \
                               : make_uint2(0u, 0u);                            \
                au0 = u.x; au1 = u.y;                                           \
            } else {                                                            \
                float4 v = aval ? *(const float4*)(xr + (kk))                   \
                                : make_float4(0.f, 0.f, 0.f, 0.f);              \
                au0 = pack_f16x2(v.x, v.y); au1 = pack_f16x2(v.z, v.w);         \
            }                                                                   \
        } while (0)
    #define LOAD_B(kk)                                                          \
        do {                                                                    \
            float2 l0 = *(const float2*)(Wl + (size_t)((kk) + 2 * kp) * 128 + n2);     \
            float2 l1 = *(const float2*)(Wl + (size_t)((kk) + 2 * kp + 1) * 128 + n2); \
            rbl = make_float4(l0.x, l0.y, l1.x, l1.y);                          \
            float2 r0 = *(const float2*)(Wr + (size_t)((kk) + 2 * kp) * 128 + n2);     \
            float2 r1 = *(const float2*)(Wr + (size_t)((kk) + 2 * kp + 1) * 128 + n2); \
            rbr = make_float4(r0.x, r0.y, r1.x, r1.y);                          \
        } while (0)
    #define STORE_AB(buf)                                                       \
        do {                                                                    \
            unsigned* a = As + (buf) * AS_BUF + arow * 12 + (acol4 >> 1);       \
            a[0] = au0; a[1] = au1;                                             \
            unsigned* b0 = Bs + (buf) * BS_BUF + n2 * 12 + kp;                  \
            b0[0]  = pack_f16x2(rbl.x, rbl.z);                                  \
            b0[12] = pack_f16x2(rbl.y, rbl.w);                                  \
            unsigned* b1 = Bs + (buf) * BS_BUF + BS_MAT + n2 * 12 + kp;         \
            b1[0]  = pack_f16x2(rbr.x, rbr.z);                                  \
            b1[12] = pack_f16x2(rbr.y, rbr.w);                                  \
        } while (0)

    // ---- prologue: chunk 0 load+store, chunk 1 load ----
    LOAD_A(0); LOAD_B(0);
    STORE_AB(0);
    LOAD_A(16); LOAD_B(16);
    __syncthreads();

    #pragma unroll
    for (int ci = 0; ci < 8; ci++) {
        int cur = ci & 1, nxt = cur ^ 1;

        // STS chunk ci+1 (regs -> buf nxt)
        if (ci < 7) STORE_AB(nxt);
        // LDG chunk ci+2 into regs
        if (ci < 6) { int kk = (ci + 2) * 16; LOAD_A(kk); LOAD_B(kk); }

        // MMA over buf cur: one k16 step
        const unsigned* Ac = As + cur * AS_BUF;
        const unsigned* Bc = Bs + cur * BS_BUF + mat * BS_MAT;
        {
            unsigned a[2][4], b[8][2];
            #pragma unroll
            for (int mi = 0; mi < 2; mi++) {
                int r = wm * 32 + mi * 16 + gid;
                a[mi][0] = Ac[r * 12 + tig];
                a[mi][1] = Ac[(r + 8) * 12 + tig];
                a[mi][2] = Ac[r * 12 + tig + 4];
                a[mi][3] = Ac[(r + 8) * 12 + tig + 4];
            }
            #pragma unroll
            for (int ni = 0; ni < 8; ni++) {
                int col = wn * 64 + ni * 8 + gid;
                b[ni][0] = Bc[col * 12 + tig];
                b[ni][1] = Bc[col * 12 + tig + 4];
            }
            #pragma unroll
            for (int mi = 0; mi < 2; mi++)
                #pragma unroll
                for (int ni = 0; ni < 8; ni++)
                    mma_f16(c[mi][ni], a[mi], b[ni]);
        }
        if (ci < 7) __syncthreads();
    }

    // epilogue
    if (mat == 0) {
        #pragma unroll
        for (int mi = 0; mi < 2; mi++) {
            int r = row0 + wm * 32 + mi * 16 + gid;
            #pragma unroll
            for (int ni = 0; ni < 8; ni++) {
                int cl = wn * 64 + ni * 8 + tig * 2;
                if (r < n)
                    g_pb[(size_t)r * 64 + (cl >> 1)] = pack_bf16x2(c[mi][ni][0], c[mi][ni][1]);
                if (r + 8 < n)
                    g_pb[(size_t)(r + 8) * 64 + (cl >> 1)] = pack_bf16x2(c[mi][ni][2], c[mi][ni][3]);
            }
        }
    } else {
        #pragma unroll
        for (int mi = 0; mi < 2; mi++) {
            int r = row0 + wm * 32 + mi * 16 + gid;
            #pragma unroll
            for (int ni = 0; ni < 8; ni++) {
                int cl = wn * 64 + ni * 8 + tig * 2;
                if (r < n)
                    *(float2*)(g_q + (size_t)r * 128 + cl) = make_float2(c[mi][ni][0], c[mi][ni][1]);
                if (r + 8 < n)
                    *(float2*)(g_q + (size_t)(r + 8) * 128 + cl) = make_float2(c[mi][ni][2], c[mi][ni][3]);
            }
        }
    }
}

// ---------------- aggregation: out = [relu]( mean_agg(Pb) + b + Q ) ---------
// osel=0: layer 1 -> relu, write g_hh as packed f16x2.  osel=1: fp32 d_out.
__global__ void k_agg(const float* __restrict__ bias, float* __restrict__ oext,
                      int osel) {
    int w = (blockIdx.x * blockDim.x + threadIdx.x) >> 5;
    if (w >= N_NODES) return;
    const unsigned* __restrict__ P = g_pb;
    const float* __restrict__ Q = g_q;

    int lane = threadIdx.x & 31;
    int s0 = g_offs[w], s1 = g_offs[w + 1];

    float4 acc0 = make_float4(0.f, 0.f, 0.f, 0.f);
    float4 acc1 = make_float4(0.f, 0.f, 0.f, 0.f);
    int e = s0;
    for (; e + 8 <= s1; e += 8) {
        int idx[8];
        #pragma unroll
        for (int j = 0; j < 8; j++) idx[j] = g_esrc[e + j];
        uint2 u[8];
        #pragma unroll
        for (int j = 0; j < 8; j++)
            u[j] = ((const uint2*)(P + (size_t)idx[j] * 64))[lane];
        #pragma unroll
        for (int j = 0; j < 8; j += 2) {
            acc0.x += bf_lo(u[j].x) + bf_lo(u[j + 1].x);
            acc0.y += bf_hi(u[j].x) + bf_hi(u[j + 1].x);
            acc0.z += bf_lo(u[j].y) + bf_lo(u[j + 1].y);
            acc0.w += bf_hi(u[j].y) + bf_hi(u[j + 1].y);
        }
    }
    for (; e + 2 <= s1; e += 2) {
        int i0 = g_esrc[e], i1 = g_esrc[e + 1];
        uint2 u0 = ((const uint2*)(P + (size_t)i0 * 64))[lane];
        uint2 u1 = ((const uint2*)(P + (size_t)i1 * 64))[lane];
        acc1.x += bf_lo(u0.x) + bf_lo(u1.x);
        acc1.y += bf_hi(u0.x) + bf_hi(u1.x);
        acc1.z += bf_lo(u0.y) + bf_lo(u1.y);
        acc1.w += bf_hi(u0.y) + bf_hi(u1.y);
    }
    if (e < s1) {
        int i0 = g_esrc[e];
        uint2 u0 = ((const uint2*)(P + (size_t)i0 * 64))[lane];
        acc1.x += bf_lo(u0.x); acc1.y += bf_hi(u0.x);
        acc1.z += bf_lo(u0.y); acc1.w += bf_hi(u0.y);
    }
    acc0.x += acc1.x; acc0.y += acc1.y; acc0.z += acc1.z; acc0.w += acc1.w;

    int deg = s1 - s0;
    float scale = 1.0f / (float)(deg > 0 ? deg : 1);
    float4 qv = ((const float4*)(Q + (size_t)w * 128))[lane];
    float4 bv = ((const float4*)bias)[lane];
    float4 r;
    r.x = fmaf(acc0.x, scale, bv.x + qv.x);
    r.y = fmaf(acc0.y, scale, bv.y + qv.y);
    r.z = fmaf(acc0.z, scale, bv.z + qv.z);
    r.w = fmaf(acc0.w, scale, bv.w + qv.w);
    if (osel == 0) {
        // layer 1: relu + fp16 store into g_hh (packed pair layout = GEMM A layout)
        r.x = fmaxf(r.x, 0.f); r.y = fmaxf(r.y, 0.f);
        r.z = fmaxf(r.z, 0.f); r.w = fmaxf(r.w, 0.f);
        ((uint2*)(g_hh + (size_t)w * 64))[lane] =
            make_uint2(pack_f16x2(r.x, r.y), pack_f16x2(r.z, r.w));
    } else {
        ((float4*)(oext + (size_t)w * 128))[lane] = r;
    }
}

// ---------------- launch -----------------------------------------------------
// Fork/join: CSR build runs concurrently with the tensor-bound GEMM1.
// Streams/events created EXACTLY ONCE (first call = correctness run); reused by
// the capture call -> no driver-pool growth can outlive graph teardown.
extern "C" void kernel_launch(void* const* d_in, const int* in_sizes, int n_in,
                              void* d_out, int out_size) {
    const float* x   = (const float*)d_in[0];
    const int*   ei  = (const int*)d_in[1];
    const float* W1l = (const float*)d_in[2];
    const float* b1  = (const float*)d_in[3];
    const float* W1r = (const float*)d_in[4];
    const float* W2l = (const float*)d_in[5];
    const float* b2  = (const float*)d_in[6];
    const float* W2r = (const float*)d_in[7];
    float* out = (float*)d_out;

    const int GEMM_GRID = (N_NODES + 127) / 128;      // 782
    const int EDGE_GRID = (N_EDGES + 255) / 256;
    const int AGG_GRID  = (N_NODES * 32 + 255) / 256;

    static cudaStream_t s1 = nullptr;
    static cudaEvent_t evFork = nullptr, evCSR = nullptr;
    if (s1 == nullptr) {
        cudaStreamCreateWithFlags(&s1, cudaStreamNonBlocking);
        cudaEventCreateWithFlags(&evFork, cudaEventDisableTiming);
        cudaEventCreateWithFlags(&evCSR, cudaEventDisableTiming);
        cudaFuncSetAttribute(k_gemm2, cudaFuncAttributeMaxDynamicSharedMemorySize, GEMM_SMEM);
    }

    // fork
    cudaEventRecord(evFork, 0);
    cudaStreamWaitEvent(s1, evFork, 0);

    // ---- branch A (s1): CSR build (dst-grouped pull lists) ----
    k_detect<<<(N_NODES + 255) / 256, 256, 0, s1>>>(ei);
    k_hist<<<EDGE_GRID, 256, 0, s1>>>(ei);
    k_scan_blocks<<<SCAN_BLOCKS, 1024, 0, s1>>>(N_NODES);
    k_add_offs<<<SCAN_BLOCKS, 1024, 0, s1>>>(N_NODES, N_EDGES);
    k_fill<<<EDGE_GRID, 256, 0, s1>>>(ei);
    cudaEventRecord(evCSR, s1);

    // ---- branch B (stream 0): layer-1 dual GEMM (independent of CSR) ----
    k_gemm2<<<GEMM_GRID, 512, GEMM_SMEM>>>(x, 0, W1l, W1r, N_NODES);

    // join, then the dependent chain
    cudaStreamWaitEvent(0, evCSR, 0);
    k_agg<<<AGG_GRID, 256>>>(b1, out, 0);
    k_gemm2<<<GEMM_GRID, 512, GEMM_SMEM>>>((const float*)0, 1, W2l, W2r, N_NODES);
    k_agg<<<AGG_GRID, 256>>>(b2, out, 1);
}

// round 14
// speedup vs baseline: 1.3890x; 1.0184x over previous
#include <cuda_runtime.h>

#define N_NODES 100000
#define N_EDGES 1600000
#define D 128
#define SCAN_BLOCKS 98   // ceil(100000/1024)

// ---------------- scratch (static __device__, no allocation) ----------------
__device__ unsigned g_pb[(size_t)N_NODES * 64]; // X @ W_l as packed bf16x2 (agg operand)
__device__ unsigned g_qh[(size_t)N_NODES * 64]; // X @ W_r as packed f16x2 (root path)
__device__ unsigned g_hh[(size_t)N_NODES * 64]; // layer-1 output, packed f16x2
__device__ int      g_cnt[N_NODES];
__device__ int      g_offs[N_NODES + 1];
__device__ int      g_cursor[N_NODES];
__device__ int      g_bsums[SCAN_BLOCKS];
__device__ int      g_is64;
__device__ int      g_esrc[N_EDGES];

// ---------------- packing helpers --------------------------------------------
__device__ __forceinline__ unsigned pack_f16x2(float lo, float hi) {
    unsigned r;
    asm("cvt.rn.f16x2.f32 %0, %1, %2;" : "=r"(r) : "f"(hi), "f"(lo));   // hi->[31:16], lo->[15:0]
    return r;
}
__device__ __forceinline__ float2 unpack_f16x2(unsigned u) {
    float lo, hi;
    asm("{ .reg .f16 l, h; mov.b32 {l, h}, %2; cvt.f32.f16 %0, l; cvt.f32.f16 %1, h; }"
        : "=f"(lo), "=f"(hi) : "r"(u));
    return make_float2(lo, hi);
}
__device__ __forceinline__ unsigned pack_bf16x2(float lo, float hi) {
    unsigned r;
    asm("cvt.rn.bf16x2.f32 %0, %1, %2;" : "=r"(r) : "f"(hi), "f"(lo));
    return r;
}
__device__ __forceinline__ float bf_lo(unsigned u) { return __uint_as_float(u << 16); }
__device__ __forceinline__ float bf_hi(unsigned u) { return __uint_as_float(u & 0xffff0000u); }

// fp16 MMA m16n8k16, fp32 accumulate
__device__ __forceinline__ void mma_f16(float c[4], const unsigned a[4], const unsigned b[2]) {
    asm volatile(
        "mma.sync.aligned.m16n8k16.row.col.f32.f16.f16.f32 "
        "{%0,%1,%2,%3}, {%4,%5,%6,%7}, {%8,%9}, {%0,%1,%2,%3};\n"
        : "+f"(c[0]), "+f"(c[1]), "+f"(c[2]), "+f"(c[3])
        : "r"(a[0]), "r"(a[1]), "r"(a[2]), "r"(a[3]), "r"(b[0]), "r"(b[1]));
}

// ---------------- edge-index dtype detect + counter zero (merged) ------------
__global__ void k_detect(const int* __restrict__ e) {
    int i = blockIdx.x * blockDim.x + threadIdx.x;
    if (i < N_NODES) g_cnt[i] = 0;
    if (blockIdx.x == 0) {
        __shared__ int nz;
        if (threadIdx.x == 0) nz = 0;
        __syncthreads();
        if (e[2 * threadIdx.x + 1] != 0) atomicAdd(&nz, 1);
        __syncthreads();
        if (threadIdx.x == 0) g_is64 = (nz == 0) ? 1 : 0;
    }
}

__device__ __forceinline__ int load_idx(const int* __restrict__ e, long long pos, int is64) {
    return is64 ? e[2 * pos] : e[pos];
}

// ---------------- CSR build --------------------------------------------------
__global__ void k_hist(const int* __restrict__ e) {
    int i = blockIdx.x * blockDim.x + threadIdx.x;
    if (i < N_EDGES) {
        int d = load_idx(e, (long long)N_EDGES + i, g_is64);
        atomicAdd(&g_cnt[d], 1);
    }
}

__global__ void k_scan_blocks(int n) {
    __shared__ int s[1024];
    int i = blockIdx.x * 1024 + threadIdx.x;
    int v = (i < n) ? g_cnt[i] : 0;
    s[threadIdx.x] = v;
    __syncthreads();
    #pragma unroll
    for (int d = 1; d < 1024; d <<= 1) {
        int t = (threadIdx.x >= d) ? s[threadIdx.x - d] : 0;
        __syncthreads();
        s[threadIdx.x] += t;
        __syncthreads();
    }
    if (i < n) g_offs[i] = s[threadIdx.x] - v;      // exclusive within block
    if (threadIdx.x == 1023) g_bsums[blockIdx.x] = s[1023];
}

__global__ void k_add_offs(int n, int e) {
    __shared__ int base;
    if (threadIdx.x < 32) {
        int b = blockIdx.x;
        int acc = 0;
        #pragma unroll
        for (int j = 0; j < 4; j++) {
            int idx = j * 32 + threadIdx.x;
            if (idx < b) acc += g_bsums[idx];
        }
        #pragma unroll
        for (int o = 16; o > 0; o >>= 1)
            acc += __shfl_down_sync(0xffffffffu, acc, o);
        if (threadIdx.x == 0) base = acc;
    }
    __syncthreads();
    int i = blockIdx.x * 1024 + threadIdx.x;
    if (i < n) {
        int o = g_offs[i] + base;
        g_offs[i] = o;
        g_cursor[i] = o;
    }
    if (i == 0) g_offs[n] = e;
}

__global__ void k_fill(const int* __restrict__ e) {
    int i = blockIdx.x * blockDim.x + threadIdx.x;
    if (i >= N_EDGES) return;
    int is64 = g_is64;
    int d = load_idx(e, (long long)N_EDGES + i, is64);
    int s = load_idx(e, (long long)i, is64);
    int pos = atomicAdd(&g_cursor[d], 1);
    g_esrc[pos] = s;
}

// ---------------- fused dual GEMM (fp16 mma): Pb = bf16(X@Wl), Qh = f16(X@Wr)
// Round-11 structure (512 threads, 1 CTA/SM, double-buffered K pipe).
// A source: fp32 Xe (layer 1, cvt on load) or packed-f16x2 g_hh (layer 2).
// As[2][128 rows][12 u32]  (row = 16 f16 + 8 pad; stride-12 is conflict-free)
// Bs[2][2 mats][128 n][12 u32] (per n: 8 u32 of {k even, k odd} f16 pairs)
#define AS_BUF 1536            // u32 per A buffer (128*12)
#define BS_BUF 3072            // u32 per B buffer (2*128*12)
#define BS_MAT 1536            // u32 per mat (128*12)
#define GEMM_SMEM 36864        // (2*1536 + 2*3072) * 4

__global__ __launch_bounds__(512) void k_gemm2(const float* __restrict__ Xe, int xsel,
                                               const float* __restrict__ Wl,
                                               const float* __restrict__ Wr, int n) {
    extern __shared__ unsigned sm[];
    unsigned* As = sm;
    unsigned* Bs = sm + 2 * AS_BUF;

    int tid = threadIdx.x;
    int wid = tid >> 5, lane = tid & 31;
    int mat = wid >> 3;             // 0 = P, 1 = Q
    int wm = (wid & 7) >> 1;        // 0..3  (row tile)
    int wn = wid & 1;               // 0..1  (col tile)
    int gid = lane >> 2, tig = lane & 3;
    int row0 = blockIdx.x * 128;

    float c[2][8][4];
    #pragma unroll
    for (int mi = 0; mi < 2; mi++)
        #pragma unroll
        for (int ni = 0; ni < 8; ni++)
            #pragma unroll
            for (int j = 0; j < 4; j++) c[mi][ni][j] = 0.f;

    // A loader: thread -> row arow, k-quad acol4 within 16-wide chunk
    int arow = tid >> 2;            // 0..127
    int acol4 = (tid & 3) * 4;      // 0,4,8,12
    // B loader: thread -> k-pair kp, n-pair n2
    int kp = tid >> 6;              // 0..7
    int n2 = (tid & 63) * 2;        // 0..126

    const float* xr = Xe + (size_t)(row0 + arow) * 128 + acol4;
    const unsigned* hr = g_hh + (size_t)(row0 + arow) * 64 + (acol4 >> 1);
    bool aval = (row0 + arow) < n;

    unsigned au0, au1;              // A prefetch (2 packed f16x2 = 4 halves)
    float4 rbl, rbr;                // B prefetch; {Wk0[n2],Wk0[n2+1],Wk1[n2],Wk1[n2+1]}

    #define LOAD_A(kk)                                                          \
        do {                                                                    \
            if (xsel) {                                                         \
                uint2 u = aval ? *(const uint2*)(hr + ((kk) >> 1))              \
                               : make_uint2(0u, 0u);                            \
                au0 = u.x; au1 = u.y;                                           \
            } else {                                                            \
                float4 v = aval ? *(const float4*)(xr + (kk))                   \
                                : make_float4(0.f, 0.f, 0.f, 0.f);              \
                au0 = pack_f16x2(v.x, v.y); au1 = pack_f16x2(v.z, v.w);         \
            }                                                                   \
        } while (0)
    #define LOAD_B(kk)                                                          \
        do {                                                                    \
            float2 l0 = *(const float2*)(Wl + (size_t)((kk) + 2 * kp) * 128 + n2);     \
            float2 l1 = *(const float2*)(Wl + (size_t)((kk) + 2 * kp + 1) * 128 + n2); \
            rbl = make_float4(l0.x, l0.y, l1.x, l1.y);                          \
            float2 r0 = *(const float2*)(Wr + (size_t)((kk) + 2 * kp) * 128 + n2);     \
            float2 r1 = *(const float2*)(Wr + (size_t)((kk) + 2 * kp + 1) * 128 + n2); \
            rbr = make_float4(r0.x, r0.y, r1.x, r1.y);                          \
        } while (0)
    #define STORE_AB(buf)                                                       \
        do {                                                                    \
            unsigned* a = As + (buf) * AS_BUF + arow * 12 + (acol4 >> 1);       \
            a[0] = au0; a[1] = au1;                                             \
            unsigned* b0 = Bs + (buf) * BS_BUF + n2 * 12 + kp;                  \
            b0[0]  = pack_f16x2(rbl.x, rbl.z);                                  \
            b0[12] = pack_f16x2(rbl.y, rbl.w);                                  \
            unsigned* b1 = Bs + (buf) * BS_BUF + BS_MAT + n2 * 12 + kp;         \
            b1[0]  = pack_f16x2(rbr.x, rbr.z);                                  \
            b1[12] = pack_f16x2(rbr.y, rbr.w);                                  \
        } while (0)

    // ---- prologue: chunk 0 load+store, chunk 1 load ----
    LOAD_A(0); LOAD_B(0);
    STORE_AB(0);
    LOAD_A(16); LOAD_B(16);
    __syncthreads();

    #pragma unroll
    for (int ci = 0; ci < 8; ci++) {
        int cur = ci & 1, nxt = cur ^ 1;

        if (ci < 7) STORE_AB(nxt);
        if (ci < 6) { int kk = (ci + 2) * 16; LOAD_A(kk); LOAD_B(kk); }

        // MMA over buf cur: one k16 step
        const unsigned* Ac = As + cur * AS_BUF;
        const unsigned* Bc = Bs + cur * BS_BUF + mat * BS_MAT;
        {
            unsigned a[2][4], b[8][2];
            #pragma unroll
            for (int mi = 0; mi < 2; mi++) {
                int r = wm * 32 + mi * 16 + gid;
                a[mi][0] = Ac[r * 12 + tig];
                a[mi][1] = Ac[(r + 8) * 12 + tig];
                a[mi][2] = Ac[r * 12 + tig + 4];
                a[mi][3] = Ac[(r + 8) * 12 + tig + 4];
            }
            #pragma unroll
            for (int ni = 0; ni < 8; ni++) {
                int col = wn * 64 + ni * 8 + gid;
                b[ni][0] = Bc[col * 12 + tig];
                b[ni][1] = Bc[col * 12 + tig + 4];
            }
            #pragma unroll
            for (int mi = 0; mi < 2; mi++)
                #pragma unroll
                for (int ni = 0; ni < 8; ni++)
                    mma_f16(c[mi][ni], a[mi], b[ni]);
        }
        if (ci < 7) __syncthreads();
    }

    // epilogue: P -> packed bf16x2, Q -> packed f16x2
    unsigned* __restrict__ dstbuf = (mat == 0) ? g_pb : g_qh;
    #pragma unroll
    for (int mi = 0; mi < 2; mi++) {
        int r = row0 + wm * 32 + mi * 16 + gid;
        #pragma unroll
        for (int ni = 0; ni < 8; ni++) {
            int cl = wn * 64 + ni * 8 + tig * 2;
            if (mat == 0) {
                if (r < n)
                    dstbuf[(size_t)r * 64 + (cl >> 1)] = pack_bf16x2(c[mi][ni][0], c[mi][ni][1]);
                if (r + 8 < n)
                    dstbuf[(size_t)(r + 8) * 64 + (cl >> 1)] = pack_bf16x2(c[mi][ni][2], c[mi][ni][3]);
            } else {
                if (r < n)
                    dstbuf[(size_t)r * 64 + (cl >> 1)] = pack_f16x2(c[mi][ni][0], c[mi][ni][1]);
                if (r + 8 < n)
                    dstbuf[(size_t)(r + 8) * 64 + (cl >> 1)] = pack_f16x2(c[mi][ni][2], c[mi][ni][3]);
            }
        }
    }
}

// ---------------- aggregation: out = [relu]( mean_agg(Pb) + b + Qh ) --------
// osel=0: layer 1 -> relu, write g_hh as packed f16x2.  osel=1: fp32 d_out.
__global__ void k_agg(const float* __restrict__ bias, float* __restrict__ oext,
                      int osel) {
    int w = (blockIdx.x * blockDim.x + threadIdx.x) >> 5;
    if (w >= N_NODES) return;
    const unsigned* __restrict__ P = g_pb;

    int lane = threadIdx.x & 31;
    int s0 = g_offs[w], s1 = g_offs[w + 1];

    float4 acc0 = make_float4(0.f, 0.f, 0.f, 0.f);
    float4 acc1 = make_float4(0.f, 0.f, 0.f, 0.f);
    int e = s0;
    for (; e + 8 <= s1; e += 8) {
        int idx[8];
        #pragma unroll
        for (int j = 0; j < 8; j++) idx[j] = g_esrc[e + j];
        uint2 u[8];
        #pragma unroll
        for (int j = 0; j < 8; j++)
            u[j] = ((const uint2*)(P + (size_t)idx[j] * 64))[lane];
        #pragma unroll
        for (int j = 0; j < 8; j += 2) {
            acc0.x += bf_lo(u[j].x) + bf_lo(u[j + 1].x);
            acc0.y += bf_hi(u[j].x) + bf_hi(u[j + 1].x);
            acc0.z += bf_lo(u[j].y) + bf_lo(u[j + 1].y);
            acc0.w += bf_hi(u[j].y) + bf_hi(u[j + 1].y);
        }
    }
    for (; e + 2 <= s1; e += 2) {
        int i0 = g_esrc[e], i1 = g_esrc[e + 1];
        uint2 u0 = ((const uint2*)(P + (size_t)i0 * 64))[lane];
        uint2 u1 = ((const uint2*)(P + (size_t)i1 * 64))[lane];
        acc1.x += bf_lo(u0.x) + bf_lo(u1.x);
        acc1.y += bf_hi(u0.x) + bf_hi(u1.x);
        acc1.z += bf_lo(u0.y) + bf_lo(u1.y);
        acc1.w += bf_hi(u0.y) + bf_hi(u1.y);
    }
    if (e < s1) {
        int i0 = g_esrc[e];
        uint2 u0 = ((const uint2*)(P + (size_t)i0 * 64))[lane];
        acc1.x += bf_lo(u0.x); acc1.y += bf_hi(u0.x);
        acc1.z += bf_lo(u0.y); acc1.w += bf_hi(u0.y);
    }
    acc0.x += acc1.x; acc0.y += acc1.y; acc0.z += acc1.z; acc0.w += acc1.w;

    int deg = s1 - s0;
    float scale = 1.0f / (float)(deg > 0 ? deg : 1);
    uint2 qu = ((const uint2*)(g_qh + (size_t)w * 64))[lane];
    float2 q0 = unpack_f16x2(qu.x), q1 = unpack_f16x2(qu.y);
    float4 bv = ((const float4*)bias)[lane];
    float4 r;
    r.x = fmaf(acc0.x, scale, bv.x + q0.x);
    r.y = fmaf(acc0.y, scale, bv.y + q0.y);
    r.z = fmaf(acc0.z, scale, bv.z + q1.x);
    r.w = fmaf(acc0.w, scale, bv.w + q1.y);
    if (osel == 0) {
        // layer 1: relu + fp16 store into g_hh (packed pair layout = GEMM A layout)
        r.x = fmaxf(r.x, 0.f); r.y = fmaxf(r.y, 0.f);
        r.z = fmaxf(r.z, 0.f); r.w = fmaxf(r.w, 0.f);
        ((uint2*)(g_hh + (size_t)w * 64))[lane] =
            make_uint2(pack_f16x2(r.x, r.y), pack_f16x2(r.z, r.w));
    } else {
        ((float4*)(oext + (size_t)w * 128))[lane] = r;
    }
}

// ---------------- launch -----------------------------------------------------
// Fork/join: CSR build runs concurrently with the tensor-bound GEMM1.
// Streams/events created EXACTLY ONCE (first call = correctness run); reused by
// the capture call -> no driver-pool growth can outlive graph teardown.
extern "C" void kernel_launch(void* const* d_in, const int* in_sizes, int n_in,
                              void* d_out, int out_size) {
    const float* x   = (const float*)d_in[0];
    const int*   ei  = (const int*)d_in[1];
    const float* W1l = (const float*)d_in[2];
    const float* b1  = (const float*)d_in[3];
    const float* W1r = (const float*)d_in[4];
    const float* W2l = (const float*)d_in[5];
    const float* b2  = (const float*)d_in[6];
    const float* W2r = (const float*)d_in[7];
    float* out = (float*)d_out;

    const int GEMM_GRID = (N_NODES + 127) / 128;      // 782
    const int EDGE_GRID = (N_EDGES + 255) / 256;
    const int AGG_GRID  = (N_NODES * 32 + 255) / 256;

    static cudaStream_t s1 = nullptr;
    static cudaEvent_t evFork = nullptr, evCSR = nullptr;
    if (s1 == nullptr) {
        cudaStreamCreateWithFlags(&s1, cudaStreamNonBlocking);
        cudaEventCreateWithFlags(&evFork, cudaEventDisableTiming);
        cudaEventCreateWithFlags(&evCSR, cudaEventDisableTiming);
        cudaFuncSetAttribute(k_gemm2, cudaFuncAttributeMaxDynamicSharedMemorySize, GEMM_SMEM);
    }

    // fork
    cudaEventRecord(evFork, 0);
    cudaStreamWaitEvent(s1, evFork, 0);

    // ---- branch A (s1): CSR build (dst-grouped pull lists) ----
    k_detect<<<(N_NODES + 255) / 256, 256, 0, s1>>>(ei);
    k_hist<<<EDGE_GRID, 256, 0, s1>>>(ei);
    k_scan_blocks<<<SCAN_BLOCKS, 1024, 0, s1>>>(N_NODES);
    k_add_offs<<<SCAN_BLOCKS, 1024, 0, s1>>>(N_NODES, N_EDGES);
    k_fill<<<EDGE_GRID, 256, 0, s1>>>(ei);
    cudaEventRecord(evCSR, s1);

    // ---- branch B (stream 0): layer-1 dual GEMM (independent of CSR) ----
    k_gemm2<<<GEMM_GRID, 512, GEMM_SMEM>>>(x, 0, W1l, W1r, N_NODES);

    // join, then the dependent chain
    cudaStreamWaitEvent(0, evCSR, 0);
    k_agg<<<AGG_GRID, 256>>>(b1, out, 0);
    k_gemm2<<<GEMM_GRID, 512, GEMM_SMEM>>>((const float*)0, 1, W2l, W2r, N_NODES);
    k_agg<<<AGG_GRID, 256>>>(b2, out, 1);
}